// round 2
// baseline (speedup 1.0000x reference)
#include <cuda_runtime.h>
#include <math.h>

#define DIM   2048
#define HNUM  16
#define KVHN  4
#define HD    128
#define BATCH 4
#define SEQ   2048
#define MROWS (BATCH*SEQ)
#define NKV   (KVHN*HD)

typedef unsigned long long u64;

__device__ __forceinline__ u64 ffma2(u64 a, u64 b, u64 c) {
    u64 d; asm("fma.rn.f32x2 %0,%1,%2,%3;" : "=l"(d) : "l"(a), "l"(b), "l"(c)); return d;
}
__device__ __forceinline__ u64 fmul2(u64 a, u64 b) {
    u64 d; asm("mul.rn.f32x2 %0,%1,%2;" : "=l"(d) : "l"(a), "l"(b)); return d;
}
__device__ __forceinline__ u64 pk2(float lo, float hi) {
    u64 r; asm("mov.b64 %0,{%1,%2};" : "=l"(r) : "f"(lo), "f"(hi)); return r;
}
__device__ __forceinline__ float2 up2(u64 v) {
    float2 f; asm("mov.b64 {%0,%1},%2;" : "=f"(f.x), "=f"(f.y) : "l"(v)); return f;
}

__device__ float g_Q[MROWS*DIM];
__device__ float g_K[MROWS*NKV];
__device__ float g_V[MROWS*NKV];
__device__ float g_AO[MROWS*DIM];

// C[M,N] = A[M,K] @ W[N,K]^T, row-major. 128x128x16 tile, 256 thr, 8x8 micro.
__global__ __launch_bounds__(256, 2)
void gemm_nt(const float* __restrict__ A, const float* __restrict__ W,
             float* __restrict__ C, int M, int N, int K)
{
    __shared__ float As[16][132];
    __shared__ float Bs[16][132];
    const int tx = threadIdx.x & 15;
    const int ty = threadIdx.x >> 4;
    const int m0 = blockIdx.y << 7;
    const int n0 = blockIdx.x << 7;

    u64 acc2[8][4];
#pragma unroll
    for (int i = 0; i < 8; i++)
#pragma unroll
        for (int j = 0; j < 4; j++) acc2[i][j] = 0ull;

    for (int kt = 0; kt < K; kt += 16) {
#pragma unroll
        for (int p = 0; p < 2; p++) {
            int fid = p*256 + threadIdx.x;
            int row = fid >> 2;
            int c4  = (fid & 3) << 2;
            float4 av = *(const float4*)(A + (size_t)(m0+row)*K + kt + c4);
            As[c4+0][row]=av.x; As[c4+1][row]=av.y; As[c4+2][row]=av.z; As[c4+3][row]=av.w;
            float4 wv = *(const float4*)(W + (size_t)(n0+row)*K + kt + c4);
            Bs[c4+0][row]=wv.x; Bs[c4+1][row]=wv.y; Bs[c4+2][row]=wv.z; Bs[c4+3][row]=wv.w;
        }
        __syncthreads();
#pragma unroll
        for (int k = 0; k < 16; k++) {
            float4 a0 = *(const float4*)&As[k][ty*8];
            float4 a1 = *(const float4*)&As[k][ty*8+4];
            u64 b2[4];
#pragma unroll
            for (int j = 0; j < 4; j++) b2[j] = *(const u64*)&Bs[k][tx*8 + j*2];
            u64 a2[8];
            a2[0]=pk2(a0.x,a0.x); a2[1]=pk2(a0.y,a0.y); a2[2]=pk2(a0.z,a0.z); a2[3]=pk2(a0.w,a0.w);
            a2[4]=pk2(a1.x,a1.x); a2[5]=pk2(a1.y,a1.y); a2[6]=pk2(a1.z,a1.z); a2[7]=pk2(a1.w,a1.w);
#pragma unroll
            for (int i = 0; i < 8; i++)
#pragma unroll
                for (int j = 0; j < 4; j++)
                    acc2[i][j] = ffma2(a2[i], b2[j], acc2[i][j]);
        }
        __syncthreads();
    }
#pragma unroll
    for (int i = 0; i < 8; i++) {
        float2 v0=up2(acc2[i][0]), v1=up2(acc2[i][1]), v2=up2(acc2[i][2]), v3=up2(acc2[i][3]);
        float* dst = C + (size_t)(m0 + ty*8 + i)*N + n0 + tx*8;
        *(float4*)dst     = make_float4(v0.x,v0.y,v1.x,v1.y);
        *(float4*)(dst+4) = make_float4(v2.x,v2.y,v3.x,v3.y);
    }
}

// per-head RMSNorm over HD=128, one warp per row; outscale folds attn scale.
__global__ void rmsnorm_k(float* __restrict__ X, const float* __restrict__ w,
                          int total, float outscale)
{
    int gw   = (blockIdx.x*blockDim.x + threadIdx.x) >> 5;
    int lane = threadIdx.x & 31;
    if (gw >= total) return;
    float* p = X + (size_t)gw * HD;
    float4 v = *(float4*)(p + lane*4);
    float ss = v.x*v.x + v.y*v.y + v.z*v.z + v.w*v.w;
#pragma unroll
    for (int o = 16; o > 0; o >>= 1) ss += __shfl_xor_sync(0xffffffffu, ss, o);
    float inv = rsqrtf(ss * (1.0f/HD) + 1e-6f) * outscale;
    float4 wv = *(const float4*)(w + lane*4);
    v.x *= inv*wv.x; v.y *= inv*wv.y; v.z *= inv*wv.z; v.w *= inv*wv.w;
    *(float4*)(p + lane*4) = v;
}

// flash attention fp32/FFMA2: 64 q-rows per CTA, 128 kv per iter, HD=128.
#define FS_Q   0
#define FS_K   8192
#define FS_V   24576
#define FS_P   41472
#define FS_R   49792
#define FS_TOT 50880   /* floats -> 203520 B */

__global__ __launch_bounds__(256, 1)
void flash_attn(const float* __restrict__ Q, const float* __restrict__ K,
                const float* __restrict__ V, float* __restrict__ AO)
{
    extern __shared__ float sm[];
    float* Qs = sm + FS_Q;   // [64][128] swizzled
    float* Ks = sm + FS_K;   // [128][128] swizzled
    float* Vs = sm + FS_V;   // [128][132]
    float* Ps = sm + FS_P;   // [64][130]
    float* red = sm + FS_R;  // [64][17]

    const int tx = threadIdx.x & 15;
    const int ty = threadIdx.x >> 4;
    const int qt = blockIdx.x;
    const int bh = blockIdx.y;
    const int b  = bh >> 4;
    const int h  = bh & 15;
    const int kv = h >> 2;

    const float* Qg = Q + (size_t)(b*SEQ + qt*64)*DIM + h*HD;
    const float* Kg = K + (size_t)b*SEQ*NKV + kv*HD;
    const float* Vg = V + (size_t)b*SEQ*NKV + kv*HD;

#pragma unroll
    for (int p = 0; p < 8; p++) {
        int fid = p*256 + threadIdx.x;
        int row = fid >> 5;
        int c4  = fid & 31;
        float4 v = *(const float4*)(Qg + (size_t)row*DIM + c4*4);
        int pc = (c4 ^ (row >> 3)) & 31;
        *(float4*)&Qs[row*128 + pc*4] = v;
    }

    float m_r[4], l_r[4];
    u64 oacc2[4][8];
#pragma unroll
    for (int i = 0; i < 4; i++) {
        m_r[i] = -1e30f; l_r[i] = 0.f;
#pragma unroll
        for (int j = 0; j < 8; j++) oacc2[i][j] = 0ull;
    }

    const int akey = ty >> 1;

    for (int j0 = 0; j0 < SEQ; j0 += 128) {
        __syncthreads();
#pragma unroll
        for (int p = 0; p < 16; p++) {
            int fid = p*256 + threadIdx.x;
            int row = fid >> 5;
            int c4  = fid & 31;
            float4 kval = *(const float4*)(Kg + (size_t)(j0+row)*NKV + c4*4);
            int pc = (c4 ^ (row >> 3)) & 31;
            *(float4*)&Ks[row*128 + pc*4] = kval;
            float4 vval = *(const float4*)(Vg + (size_t)(j0+row)*NKV + c4*4);
            *(float4*)&Vs[row*132 + c4*4] = vval;
        }
        __syncthreads();

        // S = Q K^T (pairs along d)
        u64 sacc2[4][8];
#pragma unroll
        for (int i = 0; i < 4; i++)
#pragma unroll
            for (int j = 0; j < 8; j++) sacc2[i][j] = 0ull;

#pragma unroll 8
        for (int d = 0; d < 128; d += 2) {
            int pgrp = d >> 2;
            int sub  = d & 3;
            u64 a2[4];
#pragma unroll
            for (int i = 0; i < 4; i++) {
                int r = ty*4 + i;
                a2[i] = *(const u64*)&Qs[r*128 + ((pgrp ^ akey) & 31)*4 + sub];
            }
            u64 bb[8];
#pragma unroll
            for (int j = 0; j < 8; j++) {
                int r = tx*8 + j;
                bb[j] = *(const u64*)&Ks[r*128 + ((pgrp ^ tx) & 31)*4 + sub];
            }
#pragma unroll
            for (int i = 0; i < 4; i++)
#pragma unroll
                for (int j = 0; j < 8; j++)
                    sacc2[i][j] = ffma2(a2[i], bb[j], sacc2[i][j]);
        }
        float sc[4][8];
#pragma unroll
        for (int i = 0; i < 4; i++)
#pragma unroll
            for (int j = 0; j < 8; j++) { float2 t = up2(sacc2[i][j]); sc[i][j] = t.x + t.y; }

        // online softmax
#pragma unroll
        for (int i = 0; i < 4; i++) {
            float mv = sc[i][0];
#pragma unroll
            for (int j = 1; j < 8; j++) mv = fmaxf(mv, sc[i][j]);
            red[(ty*4+i)*17 + tx] = mv;
        }
        __syncthreads();
        float mnew[4], corr[4], tsum[4];
#pragma unroll
        for (int i = 0; i < 4; i++) {
            float mv = -1e30f;
#pragma unroll
            for (int t = 0; t < 16; t++) mv = fmaxf(mv, red[(ty*4+i)*17 + t]);
            mnew[i] = fmaxf(m_r[i], mv);
            corr[i] = __expf(m_r[i] - mnew[i]);
            float s = 0.f;
#pragma unroll
            for (int j = 0; j < 8; j++) { float pv = __expf(sc[i][j] - mnew[i]); sc[i][j] = pv; s += pv; }
            tsum[i] = s;
        }
        __syncthreads();
#pragma unroll
        for (int i = 0; i < 4; i++) {
            red[(ty*4+i)*17 + tx] = tsum[i];
#pragma unroll
            for (int j = 0; j < 8; j++) Ps[(ty*4+i)*130 + tx*8 + j] = sc[i][j];
        }
        __syncthreads();
#pragma unroll
        for (int i = 0; i < 4; i++) {
            float s = 0.f;
#pragma unroll
            for (int t = 0; t < 16; t++) s += red[(ty*4+i)*17 + t];
            l_r[i] = l_r[i]*corr[i] + s;
            m_r[i] = mnew[i];
            u64 c2 = pk2(corr[i], corr[i]);
#pragma unroll
            for (int j = 0; j < 8; j++) oacc2[i][j] = fmul2(oacc2[i][j], c2);
        }

        // O += P V (pairs along kv index)
#pragma unroll 4
        for (int jj = 0; jj < 128; jj += 2) {
            u64 a2[4];
#pragma unroll
            for (int i = 0; i < 4; i++) a2[i] = *(const u64*)&Ps[(ty*4+i)*130 + jj];
            float4 vA0 = *(const float4*)&Vs[jj*132 + tx*8];
            float4 vA1 = *(const float4*)&Vs[jj*132 + tx*8 + 4];
            float4 vB0 = *(const float4*)&Vs[(jj+1)*132 + tx*8];
            float4 vB1 = *(const float4*)&Vs[(jj+1)*132 + tx*8 + 4];
            u64 bb[8];
            bb[0]=pk2(vA0.x,vB0.x); bb[1]=pk2(vA0.y,vB0.y); bb[2]=pk2(vA0.z,vB0.z); bb[3]=pk2(vA0.w,vB0.w);
            bb[4]=pk2(vA1.x,vB1.x); bb[5]=pk2(vA1.y,vB1.y); bb[6]=pk2(vA1.z,vB1.z); bb[7]=pk2(vA1.w,vB1.w);
#pragma unroll
            for (int i = 0; i < 4; i++)
#pragma unroll
                for (int j = 0; j < 8; j++)
                    oacc2[i][j] = ffma2(a2[i], bb[j], oacc2[i][j]);
        }
    }

#pragma unroll
    for (int i = 0; i < 4; i++) {
        float invl = 1.0f / l_r[i];
        float ov[8];
#pragma unroll
        for (int j = 0; j < 8; j++) { float2 t = up2(oacc2[i][j]); ov[j] = (t.x + t.y) * invl; }
        float* dst = AO + (size_t)(b*SEQ + qt*64 + ty*4 + i)*DIM + h*HD + tx*8;
        *(float4*)dst     = make_float4(ov[0],ov[1],ov[2],ov[3]);
        *(float4*)(dst+4) = make_float4(ov[4],ov[5],ov[6],ov[7]);
    }
}

extern "C" void kernel_launch(void* const* d_in, const int* in_sizes, int n_in,
                              void* d_out, int out_size)
{
    (void)in_sizes; (void)n_in; (void)out_size;
    const float* q   = (const float*)d_in[0];
    const float* k   = (const float*)d_in[1];
    const float* v   = (const float*)d_in[2];
    const float* Wq  = (const float*)d_in[3];
    const float* Wk  = (const float*)d_in[4];
    const float* Wv  = (const float*)d_in[5];
    const float* Wo  = (const float*)d_in[6];
    const float* nqw = (const float*)d_in[7];
    const float* nkw = (const float*)d_in[8];
    float* out = (float*)d_out;

    void *pQ, *pK, *pV, *pAO;
    cudaGetSymbolAddress(&pQ,  g_Q);
    cudaGetSymbolAddress(&pK,  g_K);
    cudaGetSymbolAddress(&pV,  g_V);
    cudaGetSymbolAddress(&pAO, g_AO);

    cudaFuncSetAttribute(flash_attn, cudaFuncAttributeMaxDynamicSharedMemorySize, FS_TOT*4);

    gemm_nt<<<dim3(DIM/128, MROWS/128), 256>>>(q, Wq, (float*)pQ, MROWS, DIM, DIM);
    gemm_nt<<<dim3(NKV/128, MROWS/128), 256>>>(k, Wk, (float*)pK, MROWS, NKV, DIM);
    gemm_nt<<<dim3(NKV/128, MROWS/128), 256>>>(v, Wv, (float*)pV, MROWS, NKV, DIM);

    const float qscale = 1.0f / sqrtf((float)HD);
    rmsnorm_k<<<(MROWS*HNUM)/8, 256>>>((float*)pQ, nqw, MROWS*HNUM, qscale);
    rmsnorm_k<<<(MROWS*KVHN)/8, 256>>>((float*)pK, nkw, MROWS*KVHN, 1.0f);

    flash_attn<<<dim3(SEQ/64, BATCH*HNUM), 256, FS_TOT*4>>>(
        (const float*)pQ, (const float*)pK, (const float*)pV, (float*)pAO);

    gemm_nt<<<dim3(DIM/128, MROWS/128), 256>>>((const float*)pAO, Wo, out, MROWS, DIM, DIM);
}

// round 15
// speedup vs baseline: 1.3798x; 1.3798x over previous
#include <cuda_runtime.h>
#include <cuda_bf16.h>
#include <math.h>
#include <stdint.h>

#define DIM   2048
#define HNUM  16
#define KVHN  4
#define HD    128
#define BATCH 4
#define SEQ   2048
#define MROWS (BATCH*SEQ)
#define NKV   (KVHN*HD)

#define KP    6144          /* 3*DIM augmented K */
#define BKC   64            /* bf16 per chunk row = 128B */
#define NCH   (KP/BKC)      /* 96 */
#define GBM   128
#define GBN   128
#define GSTG  3
#define GSMEM (GSTG*2*16384)   /* 98304 */

typedef unsigned long long u64;
typedef unsigned int u32;

__device__ __forceinline__ u64 ffma2(u64 a, u64 b, u64 c) {
    u64 d; asm("fma.rn.f32x2 %0,%1,%2,%3;" : "=l"(d) : "l"(a), "l"(b), "l"(c)); return d;
}
__device__ __forceinline__ u64 fmul2(u64 a, u64 b) {
    u64 d; asm("mul.rn.f32x2 %0,%1,%2;" : "=l"(d) : "l"(a), "l"(b)); return d;
}
__device__ __forceinline__ u64 pk2(float lo, float hi) {
    u64 r; asm("mov.b64 %0,{%1,%2};" : "=l"(r) : "f"(lo), "f"(hi)); return r;
}
__device__ __forceinline__ float2 up2(u64 v) {
    float2 f; asm("mov.b64 {%0,%1},%2;" : "=f"(f.x), "=f"(f.y) : "l"(v)); return f;
}
__device__ __forceinline__ u32 smem_u32(const void* p) {
    u32 a; asm("{.reg .u64 t; cvta.to.shared.u64 t, %1; cvt.u32.u64 %0, t;}" : "=r"(a) : "l"(p)); return a;
}

// scratch
__device__ __nv_bfloat16 g_As[(size_t)MROWS*KP];
__device__ __nv_bfloat16 g_Ws[(size_t)DIM*KP];
__device__ float g_Q[MROWS*DIM];
__device__ float g_K[MROWS*NKV];
__device__ float g_V[MROWS*NKV];
__device__ float g_AO[MROWS*DIM];

extern __shared__ float smf[];

// ---------------------------------------------------------------------------
// split3: fp32 [rows][2048] -> bf16 [rows][6144]
//   mode 0 (activations): [hi | lo | hi]
//   mode 1 (weights):     [hi | hi | lo]
// so A'.B' = hi.hi + lo.hi + hi.lo  (the bf16 split-accumulation product)
// ---------------------------------------------------------------------------
__global__ void split3(const float* __restrict__ X, __nv_bfloat16* __restrict__ Y,
                       int rows, int mode)
{
    int t = blockIdx.x * blockDim.x + threadIdx.x;
    if (t >= rows * 512) return;
    int r = t >> 9;
    int c = (t & 511) << 2;
    float4 v = *(const float4*)(X + ((size_t)r << 11) + c);
    __nv_bfloat16 h0 = __float2bfloat16(v.x), h1 = __float2bfloat16(v.y);
    __nv_bfloat16 h2 = __float2bfloat16(v.z), h3 = __float2bfloat16(v.w);
    __nv_bfloat16 l0 = __float2bfloat16(v.x - __bfloat162float(h0));
    __nv_bfloat16 l1 = __float2bfloat16(v.y - __bfloat162float(h1));
    __nv_bfloat16 l2 = __float2bfloat16(v.z - __bfloat162float(h2));
    __nv_bfloat16 l3 = __float2bfloat16(v.w - __bfloat162float(h3));
    size_t base = (size_t)r * KP;
    __nv_bfloat162 hA; hA.x = h0; hA.y = h1;
    __nv_bfloat162 hB; hB.x = h2; hB.y = h3;
    __nv_bfloat162 lA; lA.x = l0; lA.y = l1;
    __nv_bfloat162 lB; lB.x = l2; lB.y = l3;
    // segment 0: hi
    *(__nv_bfloat162*)(Y + base + c)          = hA;
    *(__nv_bfloat162*)(Y + base + c + 2)      = hB;
    if (mode == 0) {
        // A side: [hi | lo | hi]
        *(__nv_bfloat162*)(Y + base + 2048 + c)   = lA;
        *(__nv_bfloat162*)(Y + base + 2048 + c+2) = lB;
        *(__nv_bfloat162*)(Y + base + 4096 + c)   = hA;
        *(__nv_bfloat162*)(Y + base + 4096 + c+2) = hB;
    } else {
        // B side: [hi | hi | lo]
        *(__nv_bfloat162*)(Y + base + 2048 + c)   = hA;
        *(__nv_bfloat162*)(Y + base + 2048 + c+2) = hB;
        *(__nv_bfloat162*)(Y + base + 4096 + c)   = lA;
        *(__nv_bfloat162*)(Y + base + 4096 + c+2) = lB;
    }
}

// ---------------------------------------------------------------------------
// issue one chunk's cp.async loads: A tile 128x128B + B tile 128x128B
// ---------------------------------------------------------------------------
__device__ __forceinline__ void issue_chunk(
    const __nv_bfloat16* A, const __nv_bfloat16* B,
    int m0, int n0, size_t kb, u32 sA, u32 sB, int tid)
{
#pragma unroll
    for (int j = 0; j < 4; j++) {
        int u = tid + j*256; int row = u >> 3; int bc = u & 7;
        u32 off = (u32)(row*128 + bc*16); off ^= (off >> 3) & 0x70;
        const char* src = (const char*)A + (((size_t)(m0+row)*KP + kb) << 1) + bc*16;
        asm volatile("cp.async.cg.shared.global [%0], [%1], 16;" :: "r"(sA + off), "l"(src));
    }
#pragma unroll
    for (int j = 0; j < 4; j++) {
        int u = tid + j*256; int row = u >> 3; int bc = u & 7;
        u32 off = (u32)(row*128 + bc*16); off ^= (off >> 3) & 0x70;
        const char* src = (const char*)B + (((size_t)(n0+row)*KP + kb) << 1) + bc*16;
        asm volatile("cp.async.cg.shared.global [%0], [%1], 16;" :: "r"(sB + off), "l"(src));
    }
    asm volatile("cp.async.commit_group;" ::: "memory");
}

// ---------------------------------------------------------------------------
// HMMA GEMM: C[M,Nglob] = A[M,KP]_bf16 @ B[Nglob,KP]_bf16^T, f32 accum.
// 128x128 tile, BK=64, 8 warps (2x4), warp tile 64x32, m16n8k16 mma.
// 3-stage cp.async pipeline, SW128 swizzle, ldmatrix fragments.
// ---------------------------------------------------------------------------
__global__ __launch_bounds__(256)
void gemm_mma(const __nv_bfloat16* __restrict__ A, const __nv_bfloat16* __restrict__ B,
              float* __restrict__ C, int Nglob)
{
    const u32 sb = smem_u32((char*)smf);
    const int tid  = threadIdx.x;
    const int lane = tid & 31;
    const int w    = tid >> 5;
    const int wm   = w >> 2;       // 0..1
    const int wn   = w & 3;        // 0..3
    const int m0 = blockIdx.y * GBM;
    const int n0 = blockIdx.x * GBN;

    // ldmatrix lane address components
    const int a_row = (lane & 7) + ((lane >> 3) & 1) * 8;   // = lane & 15
    const int a_kh  = (lane >> 4) & 1;
    const int b_row = (lane & 7) + ((lane >> 4) & 1) * 8;
    const int b_kh  = (lane >> 3) & 1;

    float acc[4][4][4];
#pragma unroll
    for (int i = 0; i < 4; i++)
#pragma unroll
        for (int j = 0; j < 4; j++)
#pragma unroll
            for (int r = 0; r < 4; r++) acc[i][j][r] = 0.f;

    // prologue: chunks 0,1
    issue_chunk(A, B, m0, n0, 0,   sb,           sb + GSTG*16384,           tid);
    issue_chunk(A, B, m0, n0, BKC, sb + 16384,   sb + GSTG*16384 + 16384,   tid);

    for (int i = 0; i < NCH; i++) {
        if (i + 2 < NCH) {
            int st = (i + 2) % GSTG;
            issue_chunk(A, B, m0, n0, (size_t)(i+2)*BKC,
                        sb + st*16384, sb + GSTG*16384 + st*16384, tid);
        }
        if (i < NCH-2)       asm volatile("cp.async.wait_group 2;" ::: "memory");
        else if (i == NCH-2) asm volatile("cp.async.wait_group 1;" ::: "memory");
        else                 asm volatile("cp.async.wait_group 0;" ::: "memory");
        __syncthreads();

        const u32 aB = sb + (i % GSTG)*16384;
        const u32 bB = sb + GSTG*16384 + (i % GSTG)*16384;

#pragma unroll
        for (int ks = 0; ks < 4; ks++) {
            u32 af[4][4];
#pragma unroll
            for (int mt = 0; mt < 4; mt++) {
                u32 byte = (u32)((wm*64 + mt*16 + a_row)*128 + ks*32 + a_kh*16);
                byte ^= (byte >> 3) & 0x70;
                asm volatile("ldmatrix.sync.aligned.m8n8.x4.shared.b16 {%0,%1,%2,%3}, [%4];"
                    : "=r"(af[mt][0]), "=r"(af[mt][1]), "=r"(af[mt][2]), "=r"(af[mt][3])
                    : "r"(aB + byte));
            }
            u32 bf[2][4];
#pragma unroll
            for (int p = 0; p < 2; p++) {
                u32 byte = (u32)((wn*32 + p*16 + b_row)*128 + ks*32 + b_kh*16);
                byte ^= (byte >> 3) & 0x70;
                asm volatile("ldmatrix.sync.aligned.m8n8.x4.shared.b16 {%0,%1,%2,%3}, [%4];"
                    : "=r"(bf[p][0]), "=r"(bf[p][1]), "=r"(bf[p][2]), "=r"(bf[p][3])
                    : "r"(bB + byte));
            }
#pragma unroll
            for (int mt = 0; mt < 4; mt++)
#pragma unroll
                for (int nt = 0; nt < 4; nt++) {
                    u32 b0 = bf[nt>>1][(nt&1)*2 + 0];
                    u32 b1 = bf[nt>>1][(nt&1)*2 + 1];
                    asm volatile(
                        "mma.sync.aligned.m16n8k16.row.col.f32.bf16.bf16.f32 "
                        "{%0,%1,%2,%3},{%4,%5,%6,%7},{%8,%9},{%0,%1,%2,%3};"
                        : "+f"(acc[mt][nt][0]), "+f"(acc[mt][nt][1]),
                          "+f"(acc[mt][nt][2]), "+f"(acc[mt][nt][3])
                        : "r"(af[mt][0]), "r"(af[mt][1]), "r"(af[mt][2]), "r"(af[mt][3]),
                          "r"(b0), "r"(b1));
                }
        }
        __syncthreads();
    }

    // epilogue: fragment -> gmem (float2 stores)
    const int er = lane >> 2;        // 0..7
    const int ec = (lane & 3) * 2;   // 0,2,4,6
#pragma unroll
    for (int mt = 0; mt < 4; mt++) {
#pragma unroll
        for (int nt = 0; nt < 4; nt++) {
            int row = m0 + wm*64 + mt*16 + er;
            int col = n0 + wn*32 + nt*8 + ec;
            *(float2*)&C[(size_t)row*Nglob + col]     = make_float2(acc[mt][nt][0], acc[mt][nt][1]);
            *(float2*)&C[(size_t)(row+8)*Nglob + col] = make_float2(acc[mt][nt][2], acc[mt][nt][3]);
        }
    }
}

// ---------------------------------------------------------------------------
// per-head RMSNorm
// ---------------------------------------------------------------------------
__global__ void rmsnorm_k(float* __restrict__ X, const float* __restrict__ w,
                          int total, float outscale)
{
    int gw   = (blockIdx.x*blockDim.x + threadIdx.x) >> 5;
    int lane = threadIdx.x & 31;
    if (gw >= total) return;
    float* p = X + (size_t)gw * HD;
    float4 v = *(float4*)(p + lane*4);
    float ss = v.x*v.x + v.y*v.y + v.z*v.z + v.w*v.w;
#pragma unroll
    for (int o = 16; o > 0; o >>= 1) ss += __shfl_xor_sync(0xffffffffu, ss, o);
    float inv = rsqrtf(ss * (1.0f/HD) + 1e-6f) * outscale;
    float4 wv = *(const float4*)(w + lane*4);
    v.x *= inv*wv.x; v.y *= inv*wv.y; v.z *= inv*wv.z; v.w *= inv*wv.w;
    *(float4*)(p + lane*4) = v;
}

// ---------------------------------------------------------------------------
// flash attention fp32/FFMA2 (unchanged, proven in R2)
// ---------------------------------------------------------------------------
#define FS_Q   0
#define FS_K   8192
#define FS_V   24576
#define FS_P   41472
#define FS_R   49792
#define FS_TOT 50880

__global__ __launch_bounds__(256, 1)
void flash_attn(const float* __restrict__ Q, const float* __restrict__ K,
                const float* __restrict__ V, float* __restrict__ AO)
{
    float* sm = smf;
    float* Qs = sm + FS_Q;
    float* Ks = sm + FS_K;
    float* Vs = sm + FS_V;
    float* Ps = sm + FS_P;
    float* red = sm + FS_R;

    const int tx = threadIdx.x & 15;
    const int ty = threadIdx.x >> 4;
    const int qt = blockIdx.x;
    const int bh = blockIdx.y;
    const int b  = bh >> 4;
    const int h  = bh & 15;
    const int kv = h >> 2;

    const float* Qg = Q + (size_t)(b*SEQ + qt*64)*DIM + h*HD;
    const float* Kg = K + (size_t)b*SEQ*NKV + kv*HD;
    const float* Vg = V + (size_t)b*SEQ*NKV + kv*HD;

#pragma unroll
    for (int p = 0; p < 8; p++) {
        int fid = p*256 + threadIdx.x;
        int row = fid >> 5;
        int c4  = fid & 31;
        float4 v = *(const float4*)(Qg + (size_t)row*DIM + c4*4);
        int pc = (c4 ^ (row >> 3)) & 31;
        *(float4*)&Qs[row*128 + pc*4] = v;
    }

    float m_r[4], l_r[4];
    u64 oacc2[4][8];
#pragma unroll
    for (int i = 0; i < 4; i++) {
        m_r[i] = -1e30f; l_r[i] = 0.f;
#pragma unroll
        for (int j = 0; j < 8; j++) oacc2[i][j] = 0ull;
    }

    const int akey = ty >> 1;

    for (int j0 = 0; j0 < SEQ; j0 += 128) {
        __syncthreads();
#pragma unroll
        for (int p = 0; p < 16; p++) {
            int fid = p*256 + threadIdx.x;
            int row = fid >> 5;
            int c4  = fid & 31;
            float4 kval = *(const float4*)(Kg + (size_t)(j0+row)*NKV + c4*4);
            int pc = (c4 ^ (row >> 3)) & 31;
            *(float4*)&Ks[row*128 + pc*4] = kval;
            float4 vval = *(const float4*)(Vg + (size_t)(j0+row)*NKV + c4*4);
            *(float4*)&Vs[row*132 + c4*4] = vval;
        }
        __syncthreads();

        u64 sacc2[4][8];
#pragma unroll
        for (int i = 0; i < 4; i++)
#pragma unroll
            for (int j = 0; j < 8; j++) sacc2[i][j] = 0ull;

#pragma unroll 8
        for (int d = 0; d < 128; d += 2) {
            int pgrp = d >> 2;
            int sub  = d & 3;
            u64 a2[4];
#pragma unroll
            for (int i = 0; i < 4; i++) {
                int r = ty*4 + i;
                a2[i] = *(const u64*)&Qs[r*128 + ((pgrp ^ akey) & 31)*4 + sub];
            }
            u64 bb[8];
#pragma unroll
            for (int j = 0; j < 8; j++) {
                int r = tx*8 + j;
                bb[j] = *(const u64*)&Ks[r*128 + ((pgrp ^ tx) & 31)*4 + sub];
            }
#pragma unroll
            for (int i = 0; i < 4; i++)
#pragma unroll
                for (int j = 0; j < 8; j++)
                    sacc2[i][j] = ffma2(a2[i], bb[j], sacc2[i][j]);
        }
        float sc[4][8];
#pragma unroll
        for (int i = 0; i < 4; i++)
#pragma unroll
            for (int j = 0; j < 8; j++) { float2 t = up2(sacc2[i][j]); sc[i][j] = t.x + t.y; }

#pragma unroll
        for (int i = 0; i < 4; i++) {
            float mv = sc[i][0];
#pragma unroll
            for (int j = 1; j < 8; j++) mv = fmaxf(mv, sc[i][j]);
            red[(ty*4+i)*17 + tx] = mv;
        }
        __syncthreads();
        float mnew[4], corr[4], tsum[4];
#pragma unroll
        for (int i = 0; i < 4; i++) {
            float mv = -1e30f;
#pragma unroll
            for (int t = 0; t < 16; t++) mv = fmaxf(mv, red[(ty*4+i)*17 + t]);
            mnew[i] = fmaxf(m_r[i], mv);
            corr[i] = __expf(m_r[i] - mnew[i]);
            float s = 0.f;
#pragma unroll
            for (int j = 0; j < 8; j++) { float pv = __expf(sc[i][j] - mnew[i]); sc[i][j] = pv; s += pv; }
            tsum[i] = s;
        }
        __syncthreads();
#pragma unroll
        for (int i = 0; i < 4; i++) {
            red[(ty*4+i)*17 + tx] = tsum[i];
#pragma unroll
            for (int j = 0; j < 8; j++) Ps[(ty*4+i)*130 + tx*8 + j] = sc[i][j];
        }
        __syncthreads();
#pragma unroll
        for (int i = 0; i < 4; i++) {
            float s = 0.f;
#pragma unroll
            for (int t = 0; t < 16; t++) s += red[(ty*4+i)*17 + t];
            l_r[i] = l_r[i]*corr[i] + s;
            m_r[i] = mnew[i];
            u64 c2 = pk2(corr[i], corr[i]);
#pragma unroll
            for (int j = 0; j < 8; j++) oacc2[i][j] = fmul2(oacc2[i][j], c2);
        }

#pragma unroll 4
        for (int jj = 0; jj < 128; jj += 2) {
            u64 a2[4];
#pragma unroll
            for (int i = 0; i < 4; i++) a2[i] = *(const u64*)&Ps[(ty*4+i)*130 + jj];
            float4 vA0 = *(const float4*)&Vs[jj*132 + tx*8];
            float4 vA1 = *(const float4*)&Vs[jj*132 + tx*8 + 4];
            float4 vB0 = *(const float4*)&Vs[(jj+1)*132 + tx*8];
            float4 vB1 = *(const float4*)&Vs[(jj+1)*132 + tx*8 + 4];
            u64 bb[8];
            bb[0]=pk2(vA0.x,vB0.x); bb[1]=pk2(vA0.y,vB0.y); bb[2]=pk2(vA0.z,vB0.z); bb[3]=pk2(vA0.w,vB0.w);
            bb[4]=pk2(vA1.x,vB1.x); bb[5]=pk2(vA1.y,vB1.y); bb[6]=pk2(vA1.z,vB1.z); bb[7]=pk2(vA1.w,vB1.w);
#pragma unroll
            for (int i = 0; i < 4; i++)
#pragma unroll
                for (int j = 0; j < 8; j++)
                    oacc2[i][j] = ffma2(a2[i], bb[j], oacc2[i][j]);
        }
    }

#pragma unroll
    for (int i = 0; i < 4; i++) {
        float invl = 1.0f / l_r[i];
        float ov[8];
#pragma unroll
        for (int j = 0; j < 8; j++) { float2 t = up2(oacc2[i][j]); ov[j] = (t.x + t.y) * invl; }
        float* dst = AO + (size_t)(b*SEQ + qt*64 + ty*4 + i)*DIM + h*HD + tx*8;
        *(float4*)dst     = make_float4(ov[0],ov[1],ov[2],ov[3]);
        *(float4*)(dst+4) = make_float4(ov[4],ov[5],ov[6],ov[7]);
    }
}

// ---------------------------------------------------------------------------
extern "C" void kernel_launch(void* const* d_in, const int* in_sizes, int n_in,
                              void* d_out, int out_size)
{
    (void)in_sizes; (void)n_in; (void)out_size;
    const float* q   = (const float*)d_in[0];
    const float* k   = (const float*)d_in[1];
    const float* v   = (const float*)d_in[2];
    const float* Wq  = (const float*)d_in[3];
    const float* Wk  = (const float*)d_in[4];
    const float* Wv  = (const float*)d_in[5];
    const float* Wo  = (const float*)d_in[6];
    const float* nqw = (const float*)d_in[7];
    const float* nkw = (const float*)d_in[8];
    float* out = (float*)d_out;

    void *pAs, *pWs, *pQ, *pK, *pV, *pAO;
    cudaGetSymbolAddress(&pAs, g_As);
    cudaGetSymbolAddress(&pWs, g_Ws);
    cudaGetSymbolAddress(&pQ,  g_Q);
    cudaGetSymbolAddress(&pK,  g_K);
    cudaGetSymbolAddress(&pV,  g_V);
    cudaGetSymbolAddress(&pAO, g_AO);
    __nv_bfloat16* As = (__nv_bfloat16*)pAs;
    __nv_bfloat16* Ws = (__nv_bfloat16*)pWs;

    cudaFuncSetAttribute(gemm_mma,   cudaFuncAttributeMaxDynamicSharedMemorySize, GSMEM);
    cudaFuncSetAttribute(flash_attn, cudaFuncAttributeMaxDynamicSharedMemorySize, FS_TOT*4);

    // Q projection
    split3<<<(MROWS*512)/256, 256>>>(q, As, MROWS, 0);
    split3<<<(DIM*512)/256,   256>>>(Wq, Ws, DIM, 1);
    gemm_mma<<<dim3(DIM/GBN, MROWS/GBM), 256, GSMEM>>>(As, Ws, (float*)pQ, DIM);
    // K projection
    split3<<<(MROWS*512)/256, 256>>>(k, As, MROWS, 0);
    split3<<<(NKV*512)/256,   256>>>(Wk, Ws, NKV, 1);
    gemm_mma<<<dim3(NKV/GBN, MROWS/GBM), 256, GSMEM>>>(As, Ws, (float*)pK, NKV);
    // V projection
    split3<<<(MROWS*512)/256, 256>>>(v, As, MROWS, 0);
    split3<<<(NKV*512)/256,   256>>>(Wv, Ws, NKV, 1);
    gemm_mma<<<dim3(NKV/GBN, MROWS/GBM), 256, GSMEM>>>(As, Ws, (float*)pV, NKV);

    const float qscale = 1.0f / sqrtf((float)HD);
    rmsnorm_k<<<(MROWS*HNUM)/8, 256>>>((float*)pQ, nqw, MROWS*HNUM, qscale);
    rmsnorm_k<<<(MROWS*KVHN)/8, 256>>>((float*)pK, nkw, MROWS*KVHN, 1.0f);

    flash_attn<<<dim3(SEQ/64, BATCH*HNUM), 256, FS_TOT*4>>>(
        (const float*)pQ, (const float*)pK, (const float*)pV, (float*)pAO);

    // output projection
    split3<<<(MROWS*512)/256, 256>>>((const float*)pAO, As, MROWS, 0);
    split3<<<(DIM*512)/256,   256>>>(Wo, Ws, DIM, 1);
    gemm_mma<<<dim3(DIM/GBN, MROWS/GBM), 256, GSMEM>>>(As, Ws, out, DIM);
}

// round 17
// speedup vs baseline: 2.6412x; 1.9141x over previous
#include <cuda_runtime.h>
#include <cuda_bf16.h>
#include <math.h>
#include <stdint.h>

#define DIM   2048
#define HNUM  16
#define KVHN  4
#define HD    128
#define BATCH 4
#define SEQ   2048
#define MROWS (BATCH*SEQ)
#define NKV   (KVHN*HD)

#define KP    6144
#define BKC   64
#define NCH   (KP/BKC)
#define GBM   128
#define GBN   128
#define GSTG  3
#define GSMEM (GSTG*2*16384)

typedef unsigned long long u64;
typedef unsigned int u32;

__device__ __forceinline__ u32 smem_u32(const void* p) {
    u32 a; asm("{.reg .u64 t; cvta.to.shared.u64 t, %1; cvt.u32.u64 %0, t;}" : "=r"(a) : "l"(p)); return a;
}

// scratch
__device__ __nv_bfloat16 g_As[(size_t)MROWS*KP];
__device__ __nv_bfloat16 g_Ws[(size_t)DIM*KP];
__device__ float g_Q[MROWS*DIM];
__device__ float g_K[MROWS*NKV];
__device__ float g_V[MROWS*NKV];
__device__ float g_AO[MROWS*DIM];
__device__ __nv_bfloat16 g_Qhi[(size_t)MROWS*DIM];
__device__ __nv_bfloat16 g_Qlo[(size_t)MROWS*DIM];
__device__ __nv_bfloat16 g_Khi[(size_t)MROWS*NKV];
__device__ __nv_bfloat16 g_Klo[(size_t)MROWS*NKV];
__device__ __nv_bfloat16 g_Vthi[(size_t)MROWS*NKV];
__device__ __nv_bfloat16 g_Vtlo[(size_t)MROWS*NKV];

extern __shared__ float smf[];

// ---------------------------------------------------------------------------
// split3 (proven): mode 0 [hi|lo|hi], mode 1 [hi|hi|lo]
// ---------------------------------------------------------------------------
__global__ void split3(const float* __restrict__ X, __nv_bfloat16* __restrict__ Y,
                       int rows, int mode)
{
    int t = blockIdx.x * blockDim.x + threadIdx.x;
    if (t >= rows * 512) return;
    int r = t >> 9;
    int c = (t & 511) << 2;
    float4 v = *(const float4*)(X + ((size_t)r << 11) + c);
    __nv_bfloat16 h0 = __float2bfloat16(v.x), h1 = __float2bfloat16(v.y);
    __nv_bfloat16 h2 = __float2bfloat16(v.z), h3 = __float2bfloat16(v.w);
    __nv_bfloat16 l0 = __float2bfloat16(v.x - __bfloat162float(h0));
    __nv_bfloat16 l1 = __float2bfloat16(v.y - __bfloat162float(h1));
    __nv_bfloat16 l2 = __float2bfloat16(v.z - __bfloat162float(h2));
    __nv_bfloat16 l3 = __float2bfloat16(v.w - __bfloat162float(h3));
    size_t base = (size_t)r * KP;
    __nv_bfloat162 hA; hA.x = h0; hA.y = h1;
    __nv_bfloat162 hB; hB.x = h2; hB.y = h3;
    __nv_bfloat162 lA; lA.x = l0; lA.y = l1;
    __nv_bfloat162 lB; lB.x = l2; lB.y = l3;
    *(__nv_bfloat162*)(Y + base + c)          = hA;
    *(__nv_bfloat162*)(Y + base + c + 2)      = hB;
    if (mode == 0) {
        *(__nv_bfloat162*)(Y + base + 2048 + c)   = lA;
        *(__nv_bfloat162*)(Y + base + 2048 + c+2) = lB;
        *(__nv_bfloat162*)(Y + base + 4096 + c)   = hA;
        *(__nv_bfloat162*)(Y + base + 4096 + c+2) = hB;
    } else {
        *(__nv_bfloat162*)(Y + base + 2048 + c)   = hA;
        *(__nv_bfloat162*)(Y + base + 2048 + c+2) = hB;
        *(__nv_bfloat162*)(Y + base + 4096 + c)   = lA;
        *(__nv_bfloat162*)(Y + base + 4096 + c+2) = lB;
    }
}

// ---------------------------------------------------------------------------
// gemm chunk issue (proven)
// ---------------------------------------------------------------------------
__device__ __forceinline__ void issue_chunk(
    const __nv_bfloat16* A, const __nv_bfloat16* B,
    int m0, int n0, size_t kb, u32 sA, u32 sB, int tid)
{
#pragma unroll
    for (int j = 0; j < 4; j++) {
        int u = tid + j*256; int row = u >> 3; int bc = u & 7;
        u32 off = (u32)(row*128 + bc*16); off ^= (off >> 3) & 0x70;
        const char* src = (const char*)A + (((size_t)(m0+row)*KP + kb) << 1) + bc*16;
        asm volatile("cp.async.cg.shared.global [%0], [%1], 16;" :: "r"(sA + off), "l"(src));
    }
#pragma unroll
    for (int j = 0; j < 4; j++) {
        int u = tid + j*256; int row = u >> 3; int bc = u & 7;
        u32 off = (u32)(row*128 + bc*16); off ^= (off >> 3) & 0x70;
        const char* src = (const char*)B + (((size_t)(n0+row)*KP + kb) << 1) + bc*16;
        asm volatile("cp.async.cg.shared.global [%0], [%1], 16;" :: "r"(sB + off), "l"(src));
    }
    asm volatile("cp.async.commit_group;" ::: "memory");
}

// ---------------------------------------------------------------------------
// HMMA GEMM (proven)
// ---------------------------------------------------------------------------
__global__ __launch_bounds__(256)
void gemm_mma(const __nv_bfloat16* __restrict__ A, const __nv_bfloat16* __restrict__ B,
              float* __restrict__ C, int Nglob)
{
    const u32 sb = smem_u32((char*)smf);
    const int tid  = threadIdx.x;
    const int lane = tid & 31;
    const int w    = tid >> 5;
    const int wm   = w >> 2;
    const int wn   = w & 3;
    const int m0 = blockIdx.y * GBM;
    const int n0 = blockIdx.x * GBN;

    const int a_row = lane & 15;
    const int a_kh  = (lane >> 4) & 1;
    const int b_row = (lane & 7) + ((lane >> 4) & 1) * 8;
    const int b_kh  = (lane >> 3) & 1;

    float acc[4][4][4];
#pragma unroll
    for (int i = 0; i < 4; i++)
#pragma unroll
        for (int j = 0; j < 4; j++)
#pragma unroll
            for (int r = 0; r < 4; r++) acc[i][j][r] = 0.f;

    issue_chunk(A, B, m0, n0, 0,   sb,           sb + GSTG*16384,           tid);
    issue_chunk(A, B, m0, n0, BKC, sb + 16384,   sb + GSTG*16384 + 16384,   tid);

    for (int i = 0; i < NCH; i++) {
        if (i + 2 < NCH) {
            int st = (i + 2) % GSTG;
            issue_chunk(A, B, m0, n0, (size_t)(i+2)*BKC,
                        sb + st*16384, sb + GSTG*16384 + st*16384, tid);
        }
        if (i < NCH-2)       asm volatile("cp.async.wait_group 2;" ::: "memory");
        else if (i == NCH-2) asm volatile("cp.async.wait_group 1;" ::: "memory");
        else                 asm volatile("cp.async.wait_group 0;" ::: "memory");
        __syncthreads();

        const u32 aB = sb + (i % GSTG)*16384;
        const u32 bB = sb + GSTG*16384 + (i % GSTG)*16384;

#pragma unroll
        for (int ks = 0; ks < 4; ks++) {
            u32 af[4][4];
#pragma unroll
            for (int mt = 0; mt < 4; mt++) {
                u32 byte = (u32)((wm*64 + mt*16 + a_row)*128 + ks*32 + a_kh*16);
                byte ^= (byte >> 3) & 0x70;
                asm volatile("ldmatrix.sync.aligned.m8n8.x4.shared.b16 {%0,%1,%2,%3}, [%4];"
                    : "=r"(af[mt][0]), "=r"(af[mt][1]), "=r"(af[mt][2]), "=r"(af[mt][3])
                    : "r"(aB + byte));
            }
            u32 bf[2][4];
#pragma unroll
            for (int p = 0; p < 2; p++) {
                u32 byte = (u32)((wn*32 + p*16 + b_row)*128 + ks*32 + b_kh*16);
                byte ^= (byte >> 3) & 0x70;
                asm volatile("ldmatrix.sync.aligned.m8n8.x4.shared.b16 {%0,%1,%2,%3}, [%4];"
                    : "=r"(bf[p][0]), "=r"(bf[p][1]), "=r"(bf[p][2]), "=r"(bf[p][3])
                    : "r"(bB + byte));
            }
#pragma unroll
            for (int mt = 0; mt < 4; mt++)
#pragma unroll
                for (int nt = 0; nt < 4; nt++) {
                    u32 b0 = bf[nt>>1][(nt&1)*2 + 0];
                    u32 b1 = bf[nt>>1][(nt&1)*2 + 1];
                    asm volatile(
                        "mma.sync.aligned.m16n8k16.row.col.f32.bf16.bf16.f32 "
                        "{%0,%1,%2,%3},{%4,%5,%6,%7},{%8,%9},{%0,%1,%2,%3};"
                        : "+f"(acc[mt][nt][0]), "+f"(acc[mt][nt][1]),
                          "+f"(acc[mt][nt][2]), "+f"(acc[mt][nt][3])
                        : "r"(af[mt][0]), "r"(af[mt][1]), "r"(af[mt][2]), "r"(af[mt][3]),
                          "r"(b0), "r"(b1));
                }
        }
        __syncthreads();
    }

    const int er = lane >> 2;
    const int ec = (lane & 3) * 2;
#pragma unroll
    for (int mt = 0; mt < 4; mt++) {
#pragma unroll
        for (int nt = 0; nt < 4; nt++) {
            int row = m0 + wm*64 + mt*16 + er;
            int col = n0 + wn*32 + nt*8 + ec;
            *(float2*)&C[(size_t)row*Nglob + col]     = make_float2(acc[mt][nt][0], acc[mt][nt][1]);
            *(float2*)&C[(size_t)(row+8)*Nglob + col] = make_float2(acc[mt][nt][2], acc[mt][nt][3]);
        }
    }
}

// ---------------------------------------------------------------------------
// rmsnorm fused with hi/lo bf16 split
// ---------------------------------------------------------------------------
__global__ void rmsnorm_split(const float* __restrict__ X, const float* __restrict__ w,
                              __nv_bfloat16* __restrict__ Yhi, __nv_bfloat16* __restrict__ Ylo,
                              int total, float outscale)
{
    int gw   = (blockIdx.x*blockDim.x + threadIdx.x) >> 5;
    int lane = threadIdx.x & 31;
    if (gw >= total) return;
    const float* p = X + (size_t)gw * HD;
    float4 v = *(const float4*)(p + lane*4);
    float ss = v.x*v.x + v.y*v.y + v.z*v.z + v.w*v.w;
#pragma unroll
    for (int o = 16; o > 0; o >>= 1) ss += __shfl_xor_sync(0xffffffffu, ss, o);
    float inv = rsqrtf(ss * (1.0f/HD) + 1e-6f) * outscale;
    float4 wv = *(const float4*)(w + lane*4);
    float f0 = v.x*inv*wv.x, f1 = v.y*inv*wv.y, f2 = v.z*inv*wv.z, f3 = v.w*inv*wv.w;
    __nv_bfloat16 h0=__float2bfloat16(f0), h1=__float2bfloat16(f1);
    __nv_bfloat16 h2=__float2bfloat16(f2), h3=__float2bfloat16(f3);
    __nv_bfloat16 l0=__float2bfloat16(f0-__bfloat162float(h0));
    __nv_bfloat16 l1=__float2bfloat16(f1-__bfloat162float(h1));
    __nv_bfloat16 l2=__float2bfloat16(f2-__bfloat162float(h2));
    __nv_bfloat16 l3=__float2bfloat16(f3-__bfloat162float(h3));
    __nv_bfloat162 hp0; hp0.x=h0; hp0.y=h1;
    __nv_bfloat162 hp1; hp1.x=h2; hp1.y=h3;
    __nv_bfloat162 lp0; lp0.x=l0; lp0.y=l1;
    __nv_bfloat162 lp1; lp1.x=l2; lp1.y=l3;
    size_t o0 = (size_t)gw*HD + lane*4;
    *(__nv_bfloat162*)(Yhi + o0)     = hp0;
    *(__nv_bfloat162*)(Yhi + o0 + 2) = hp1;
    *(__nv_bfloat162*)(Ylo + o0)     = lp0;
    *(__nv_bfloat162*)(Ylo + o0 + 2) = lp1;
}

// ---------------------------------------------------------------------------
// V transpose + split
// ---------------------------------------------------------------------------
__global__ void vtsplit(const float* __restrict__ V,
                        __nv_bfloat16* __restrict__ Thi, __nv_bfloat16* __restrict__ Tlo)
{
    __shared__ float tile[32][33];
    int b  = blockIdx.z;
    int bs = blockIdx.x;
    int bc = blockIdx.y;
    int tx = threadIdx.x & 31, ty = threadIdx.x >> 5;
#pragma unroll
    for (int yy = 0; yy < 4; yy++) {
        int r = ty*4 + yy;
        tile[r][tx] = V[((size_t)(b*SEQ + bs*32 + r))*NKV + bc*32 + tx];
    }
    __syncthreads();
#pragma unroll
    for (int yy = 0; yy < 4; yy++) {
        int c = ty*4 + yy;
        float val = tile[tx][c];
        __nv_bfloat16 h = __float2bfloat16(val);
        __nv_bfloat16 l = __float2bfloat16(val - __bfloat162float(h));
        size_t o = ((size_t)(b*NKV + bc*32 + c))*SEQ + bs*32 + tx;
        Thi[o] = h; Tlo[o] = l;
    }
}

// ---------------------------------------------------------------------------
// flash attention, HMMA + bf16 split-accumulation
// ---------------------------------------------------------------------------
#define FQHI  0
#define FQLO  16384
#define FKV0  32768
#define OKHI  0
#define OKLO  16384
#define OVHI  32768
#define OVLO  49152
#define FSB   163840
#define FPHI  180224
#define FPLO  188416
#define FRED  196608
#define FCORR 200960
#define FLROW 201216
#define FTOT  201472

__device__ __forceinline__ void flash_issue(
    const __nv_bfloat16* Khi, const __nv_bfloat16* Klo,
    const __nv_bfloat16* Vthi, const __nv_bfloat16* Vtlo,
    u32 sbase, int b, int kv, int j0, int tid)
{
#pragma unroll
    for (int j = 0; j < 4; j++) {
        int u = tid + j*256;
        int row = u >> 4, q = u & 15, ch = q >> 3, bc = q & 7;
        u32 off = (u32)(row*128 + bc*16); off ^= (off >> 3) & 0x70;
        size_t so = ((size_t)(b*SEQ + j0 + row)*NKV + kv*HD + ch*64 + bc*8) << 1;
        asm volatile("cp.async.cg.shared.global [%0], [%1], 16;"
            :: "r"(sbase + OKHI + ch*8192 + off), "l"((const char*)Khi + so));
        asm volatile("cp.async.cg.shared.global [%0], [%1], 16;"
            :: "r"(sbase + OKLO + ch*8192 + off), "l"((const char*)Klo + so));
    }
#pragma unroll
    for (int j = 0; j < 4; j++) {
        int u = tid + j*256;
        int row = u >> 3, bc = u & 7;
        u32 off = (u32)(row*128 + bc*16); off ^= (off >> 3) & 0x70;
        size_t so = ((size_t)(b*NKV + kv*HD + row)*SEQ + j0 + bc*8) << 1;
        asm volatile("cp.async.cg.shared.global [%0], [%1], 16;"
            :: "r"(sbase + OVHI + off), "l"((const char*)Vthi + so));
        asm volatile("cp.async.cg.shared.global [%0], [%1], 16;"
            :: "r"(sbase + OVLO + off), "l"((const char*)Vtlo + so));
    }
    asm volatile("cp.async.commit_group;" ::: "memory");
}

__global__ __launch_bounds__(256, 1)
void flash_mma(const __nv_bfloat16* __restrict__ Qhi, const __nv_bfloat16* __restrict__ Qlo,
               const __nv_bfloat16* __restrict__ Khi, const __nv_bfloat16* __restrict__ Klo,
               const __nv_bfloat16* __restrict__ Vthi, const __nv_bfloat16* __restrict__ Vtlo,
               float* __restrict__ AO)
{
    char* sm = (char*)smf;
    const u32 sb = smem_u32(sm);
    const int tid = threadIdx.x, lane = tid & 31, w = tid >> 5;
    const int wm = w >> 2, wn = w & 3;
    const int tx = tid & 15, ty = tid >> 4;
    const int qt = blockIdx.x, bh = blockIdx.y;
    const int b = bh >> 4, h = bh & 15, kv = h >> 2;
    const int grow0 = b*SEQ + qt*64;

    const int a_row = lane & 15;
    const int a_kh  = (lane >> 4) & 1;
    const int b_row = (lane & 7) + ((lane >> 4) & 1) * 8;
    const int b_kh  = (lane >> 3) & 1;
    const int er = lane >> 2, ec = (lane & 3) * 2;

#pragma unroll
    for (int j = 0; j < 4; j++) {
        int u = tid + j*256;
        int row = u >> 4, q = u & 15, ch = q >> 3, bc = q & 7;
        size_t gof = (size_t)(grow0 + row)*DIM + h*HD + ch*64 + bc*8;
        uint4 hv = *(const uint4*)(Qhi + gof);
        uint4 lv = *(const uint4*)(Qlo + gof);
        u32 off = (u32)(row*128 + bc*16); off ^= (off >> 3) & 0x70;
        *(uint4*)(sm + FQHI + ch*8192 + off) = hv;
        *(uint4*)(sm + FQLO + ch*8192 + off) = lv;
    }

    flash_issue(Khi, Klo, Vthi, Vtlo, sb + FKV0, b, kv, 0, tid);

    float m_r[4], l_r[4];
#pragma unroll
    for (int i = 0; i < 4; i++) { m_r[i] = -1e30f; l_r[i] = 0.f; }
    float oacc[2][4][4];
#pragma unroll
    for (int i = 0; i < 2; i++)
#pragma unroll
        for (int j = 0; j < 4; j++)
#pragma unroll
            for (int r = 0; r < 4; r++) oacc[i][j][r] = 0.f;

    float* Sb      = (float*)(sm + FSB);
    float* red     = (float*)(sm + FRED);
    float* corrbuf = (float*)(sm + FCORR);
    float* lrow    = (float*)(sm + FLROW);

    for (int t = 0; t < 32; t++) {
        if (t + 1 < 32) {
            flash_issue(Khi, Klo, Vthi, Vtlo, sb + FKV0 + ((t+1)&1)*65536, b, kv, (t+1)*64, tid);
            asm volatile("cp.async.wait_group 1;" ::: "memory");
        } else {
            asm volatile("cp.async.wait_group 0;" ::: "memory");
        }
        __syncthreads();

        const u32 kvb = FKV0 + (t&1)*65536;

        float accS[2][2][4];
#pragma unroll
        for (int i = 0; i < 2; i++)
#pragma unroll
            for (int j = 0; j < 2; j++)
#pragma unroll
                for (int r = 0; r < 4; r++) accS[i][j][r] = 0.f;

#pragma unroll
        for (int pass = 0; pass < 3; pass++) {
            const u32 Abase = (pass == 1) ? (u32)FQLO : (u32)FQHI;
            const u32 Bbase = kvb + ((pass == 2) ? (u32)OKLO : (u32)OKHI);
#pragma unroll
            for (int c = 0; c < 2; c++) {
#pragma unroll
                for (int ks = 0; ks < 4; ks++) {
                    u32 af[2][4];
#pragma unroll
                    for (int mt = 0; mt < 2; mt++) {
                        u32 byte = (u32)((wm*32 + mt*16 + a_row)*128 + ks*32 + a_kh*16);
                        byte ^= (byte >> 3) & 0x70;
                        asm volatile("ldmatrix.sync.aligned.m8n8.x4.shared.b16 {%0,%1,%2,%3}, [%4];"
                            : "=r"(af[mt][0]), "=r"(af[mt][1]), "=r"(af[mt][2]), "=r"(af[mt][3])
                            : "r"(sb + Abase + c*8192 + byte));
                    }
                    u32 bf4[4];
                    {
                        u32 byte = (u32)((wn*16 + b_row)*128 + ks*32 + b_kh*16);
                        byte ^= (byte >> 3) & 0x70;
                        asm volatile("ldmatrix.sync.aligned.m8n8.x4.shared.b16 {%0,%1,%2,%3}, [%4];"
                            : "=r"(bf4[0]), "=r"(bf4[1]), "=r"(bf4[2]), "=r"(bf4[3])
                            : "r"(sb + Bbase + c*8192 + byte));
                    }
#pragma unroll
                    for (int mt = 0; mt < 2; mt++)
#pragma unroll
                        for (int nt = 0; nt < 2; nt++) {
                            asm volatile(
                                "mma.sync.aligned.m16n8k16.row.col.f32.bf16.bf16.f32 "
                                "{%0,%1,%2,%3},{%4,%5,%6,%7},{%8,%9},{%0,%1,%2,%3};"
                                : "+f"(accS[mt][nt][0]), "+f"(accS[mt][nt][1]),
                                  "+f"(accS[mt][nt][2]), "+f"(accS[mt][nt][3])
                                : "r"(af[mt][0]), "r"(af[mt][1]), "r"(af[mt][2]), "r"(af[mt][3]),
                                  "r"(bf4[nt*2]), "r"(bf4[nt*2+1]));
                        }
                }
            }
        }
#pragma unroll
        for (int mt = 0; mt < 2; mt++) {
            int r1 = wm*32 + mt*16 + er;
#pragma unroll
            for (int nt = 0; nt < 2; nt++) {
                int col = wn*16 + nt*8 + ec;
                *(float2*)&Sb[r1*64 + col]     = make_float2(accS[mt][nt][0], accS[mt][nt][1]);
                *(float2*)&Sb[(r1+8)*64 + col] = make_float2(accS[mt][nt][2], accS[mt][nt][3]);
            }
        }
        __syncthreads();

        float sc[4][4];
#pragma unroll
        for (int i = 0; i < 4; i++)
#pragma unroll
            for (int jj = 0; jj < 4; jj++) sc[i][jj] = Sb[(ty*4+i)*64 + tx*4 + jj];
#pragma unroll
        for (int i = 0; i < 4; i++) {
            float mv = fmaxf(fmaxf(sc[i][0], sc[i][1]), fmaxf(sc[i][2], sc[i][3]));
            red[(ty*4+i)*17 + tx] = mv;
        }
        __syncthreads();
        float corr[4], tsum[4];
#pragma unroll
        for (int i = 0; i < 4; i++) {
            float mv = -1e30f;
#pragma unroll
            for (int t16 = 0; t16 < 16; t16++) mv = fmaxf(mv, red[(ty*4+i)*17 + t16]);
            float mnew = fmaxf(m_r[i], mv);
            corr[i] = __expf(m_r[i] - mnew);
            float s = 0.f;
#pragma unroll
            for (int jj = 0; jj < 4; jj++) { float pv = __expf(sc[i][jj] - mnew); sc[i][jj] = pv; s += pv; }
            tsum[i] = s;
            m_r[i] = mnew;
        }
        __syncthreads();
#pragma unroll
        for (int i = 0; i < 4; i++) {
            int row = ty*4 + i;
            red[row*17 + tx] = tsum[i];
            corrbuf[row] = corr[i];
            __nv_bfloat16 h0=__float2bfloat16(sc[i][0]), h1=__float2bfloat16(sc[i][1]);
            __nv_bfloat16 h2=__float2bfloat16(sc[i][2]), h3=__float2bfloat16(sc[i][3]);
            __nv_bfloat16 q0=__float2bfloat16(sc[i][0]-__bfloat162float(h0));
            __nv_bfloat16 q1=__float2bfloat16(sc[i][1]-__bfloat162float(h1));
            __nv_bfloat16 q2=__float2bfloat16(sc[i][2]-__bfloat162float(h2));
            __nv_bfloat16 q3=__float2bfloat16(sc[i][3]-__bfloat162float(h3));
            u32 raw = (u32)(row*128 + tx*8);
            u32 key = (raw >> 3) & 0x70;
            __nv_bfloat162 hp0; hp0.x=h0; hp0.y=h1;
            __nv_bfloat162 hp1; hp1.x=h2; hp1.y=h3;
            __nv_bfloat162 lp0; lp0.x=q0; lp0.y=q1;
            __nv_bfloat162 lp1; lp1.x=q2; lp1.y=q3;
            *(__nv_bfloat162*)(sm + FPHI + (raw^key))     = hp0;
            *(__nv_bfloat162*)(sm + FPHI + ((raw+4)^key)) = hp1;
            *(__nv_bfloat162*)(sm + FPLO + (raw^key))     = lp0;
            *(__nv_bfloat162*)(sm + FPLO + ((raw+4)^key)) = lp1;
        }
        __syncthreads();
#pragma unroll
        for (int i = 0; i < 4; i++) {
            float s = 0.f;
#pragma unroll
            for (int t16 = 0; t16 < 16; t16++) s += red[(ty*4+i)*17 + t16];
            l_r[i] = l_r[i]*corr[i] + s;
        }

#pragma unroll
        for (int mt = 0; mt < 2; mt++) {
            int r1 = wm*32 + mt*16 + er;
            float c1 = corrbuf[r1], c2 = corrbuf[r1+8];
#pragma unroll
            for (int nt = 0; nt < 4; nt++) {
                oacc[mt][nt][0] *= c1; oacc[mt][nt][1] *= c1;
                oacc[mt][nt][2] *= c2; oacc[mt][nt][3] *= c2;
            }
        }

#pragma unroll
        for (int pass = 0; pass < 3; pass++) {
            const u32 Abase = (pass == 1) ? (u32)FPLO : (u32)FPHI;
            const u32 Bbase = kvb + ((pass == 2) ? (u32)OVLO : (u32)OVHI);
#pragma unroll
            for (int ks = 0; ks < 4; ks++) {
                u32 af[2][4];
#pragma unroll
                for (int mt = 0; mt < 2; mt++) {
                    u32 byte = (u32)((wm*32 + mt*16 + a_row)*128 + ks*32 + a_kh*16);
                    byte ^= (byte >> 3) & 0x70;
                    asm volatile("ldmatrix.sync.aligned.m8n8.x4.shared.b16 {%0,%1,%2,%3}, [%4];"
                        : "=r"(af[mt][0]), "=r"(af[mt][1]), "=r"(af[mt][2]), "=r"(af[mt][3])
                        : "r"(sb + Abase + byte));
                }
                u32 bfv[2][4];
#pragma unroll
                for (int p = 0; p < 2; p++) {
                    u32 byte = (u32)((wn*32 + p*16 + b_row)*128 + ks*32 + b_kh*16);
                    byte ^= (byte >> 3) & 0x70;
                    asm volatile("ldmatrix.sync.aligned.m8n8.x4.shared.b16 {%0,%1,%2,%3}, [%4];"
                        : "=r"(bfv[p][0]), "=r"(bfv[p][1]), "=r"(bfv[p][2]), "=r"(bfv[p][3])
                        : "r"(sb + Bbase + byte));
                }
#pragma unroll
                for (int mt = 0; mt < 2; mt++)
#pragma unroll
                    for (int nt = 0; nt < 4; nt++) {
                        u32 b0 = bfv[nt>>1][(nt&1)*2 + 0];
                        u32 b1 = bfv[nt>>1][(nt&1)*2 + 1];
                        asm volatile(
                            "mma.sync.aligned.m16n8k16.row.col.f32.bf16.bf16.f32 "
                            "{%0,%1,%2,%3},{%4,%5,%6,%7},{%8,%9},{%0,%1,%2,%3};"
                            : "+f"(oacc[mt][nt][0]), "+f"(oacc[mt][nt][1]),
                              "+f"(oacc[mt][nt][2]), "+f"(oacc[mt][nt][3])
                            : "r"(af[mt][0]), "r"(af[mt][1]), "r"(af[mt][2]), "r"(af[mt][3]),
                              "r"(b0), "r"(b1));
                    }
            }
        }
        __syncthreads();
    }

#pragma unroll
    for (int i = 0; i < 4; i++) lrow[ty*4 + i] = l_r[i];
    __syncthreads();
#pragma unroll
    for (int mt = 0; mt < 2; mt++) {
        int r1 = wm*32 + mt*16 + er;
        float il1 = 1.0f / lrow[r1], il2 = 1.0f / lrow[r1+8];
#pragma unroll
        for (int nt = 0; nt < 4; nt++) {
            int col = h*HD + wn*32 + nt*8 + ec;
            *(float2*)&AO[(size_t)(grow0 + r1)*DIM + col] =
                make_float2(oacc[mt][nt][0]*il1, oacc[mt][nt][1]*il1);
            *(float2*)&AO[(size_t)(grow0 + r1 + 8)*DIM + col] =
                make_float2(oacc[mt][nt][2]*il2, oacc[mt][nt][3]*il2);
        }
    }
}

// ---------------------------------------------------------------------------
extern "C" void kernel_launch(void* const* d_in, const int* in_sizes, int n_in,
                              void* d_out, int out_size)
{
    (void)in_sizes; (void)n_in; (void)out_size;
    const float* q   = (const float*)d_in[0];
    const float* k   = (const float*)d_in[1];
    const float* v   = (const float*)d_in[2];
    const float* Wq  = (const float*)d_in[3];
    const float* Wk  = (const float*)d_in[4];
    const float* Wv  = (const float*)d_in[5];
    const float* Wo  = (const float*)d_in[6];
    const float* nqw = (const float*)d_in[7];
    const float* nkw = (const float*)d_in[8];
    float* out = (float*)d_out;

    void *pAs, *pWs, *pQ, *pK, *pV, *pAO;
    void *pQh, *pQl, *pKh, *pKl, *pVh, *pVl;
    cudaGetSymbolAddress(&pAs, g_As);
    cudaGetSymbolAddress(&pWs, g_Ws);
    cudaGetSymbolAddress(&pQ,  g_Q);
    cudaGetSymbolAddress(&pK,  g_K);
    cudaGetSymbolAddress(&pV,  g_V);
    cudaGetSymbolAddress(&pAO, g_AO);
    cudaGetSymbolAddress(&pQh, g_Qhi);
    cudaGetSymbolAddress(&pQl, g_Qlo);
    cudaGetSymbolAddress(&pKh, g_Khi);
    cudaGetSymbolAddress(&pKl, g_Klo);
    cudaGetSymbolAddress(&pVh, g_Vthi);
    cudaGetSymbolAddress(&pVl, g_Vtlo);
    __nv_bfloat16* As = (__nv_bfloat16*)pAs;
    __nv_bfloat16* Ws = (__nv_bfloat16*)pWs;

    cudaFuncSetAttribute(gemm_mma,  cudaFuncAttributeMaxDynamicSharedMemorySize, GSMEM);
    cudaFuncSetAttribute(flash_mma, cudaFuncAttributeMaxDynamicSharedMemorySize, FTOT);

    // projections
    split3<<<(MROWS*512)/256, 256>>>(q, As, MROWS, 0);
    split3<<<(DIM*512)/256,   256>>>(Wq, Ws, DIM, 1);
    gemm_mma<<<dim3(DIM/GBN, MROWS/GBM), 256, GSMEM>>>(As, Ws, (float*)pQ, DIM);
    split3<<<(MROWS*512)/256, 256>>>(k, As, MROWS, 0);
    split3<<<(NKV*512)/256,   256>>>(Wk, Ws, NKV, 1);
    gemm_mma<<<dim3(NKV/GBN, MROWS/GBM), 256, GSMEM>>>(As, Ws, (float*)pK, NKV);
    split3<<<(MROWS*512)/256, 256>>>(v, As, MROWS, 0);
    split3<<<(NKV*512)/256,   256>>>(Wv, Ws, NKV, 1);
    gemm_mma<<<dim3(NKV/GBN, MROWS/GBM), 256, GSMEM>>>(As, Ws, (float*)pV, NKV);

    // norm + split for attention operands
    const float qscale = 1.0f / sqrtf((float)HD);
    rmsnorm_split<<<(MROWS*HNUM)/8, 256>>>((const float*)pQ, nqw,
        (__nv_bfloat16*)pQh, (__nv_bfloat16*)pQl, MROWS*HNUM, qscale);
    rmsnorm_split<<<(MROWS*KVHN)/8, 256>>>((const float*)pK, nkw,
        (__nv_bfloat16*)pKh, (__nv_bfloat16*)pKl, MROWS*KVHN, 1.0f);
    vtsplit<<<dim3(SEQ/32, NKV/32, BATCH), 256>>>((const float*)pV,
        (__nv_bfloat16*)pVh, (__nv_bfloat16*)pVl);

    flash_mma<<<dim3(SEQ/64, BATCH*HNUM), 256, FTOT>>>(
        (const __nv_bfloat16*)pQh, (const __nv_bfloat16*)pQl,
        (const __nv_bfloat16*)pKh, (const __nv_bfloat16*)pKl,
        (const __nv_bfloat16*)pVh, (const __nv_bfloat16*)pVl,
        (float*)pAO);

    // output projection
    split3<<<(MROWS*512)/256, 256>>>((const float*)pAO, As, MROWS, 0);
    split3<<<(DIM*512)/256,   256>>>(Wo, Ws, DIM, 1);
    gemm_mma<<<dim3(DIM/GBN, MROWS/GBM), 256, GSMEM>>>(As, Ws, out, DIM);
}